// round 8
// baseline (speedup 1.0000x reference)
#include <cuda_runtime.h>
#include <cuda_bf16.h>
#include <cstdint>

// HopfOscillatorModule, round 8: single-launch HMMA bf16-split GEMM.
//   [P|Q](row) = [x|y](row) . M,  M 64x64 constant (built per-CTA in SMEM).
//   psi_dot_i = 2*pi*v_i + cos(psi_i)*P_i - sin(psi_i)*Q_i
// 3-chunk bf16 split (AhiBhi + AloBhi + AhiBlo), f32 accum.
// MMA k-loop reordered so Bhi fragments are loaded once per ks (40 ldm4/warp).

#define NOSC 32
#define TILE_ROWS 128
#define TWO_PI 6.283185307179586f

typedef unsigned int u32;

#define A_STRIDE 144
#define B_STRIDE 144
#define OFF_AHI 0                      // 128*144 = 18432
#define OFF_ALO 18432                  // -> 36864
#define OFF_BHI 36864                  // 64*144 = 9216 -> 46080
#define OFF_BLO 46080                  // -> 55296
#define OFF_CS  55296                  // float2[128][32] = 32768 -> 88064
#define OFF_K0  88064
#define OFF_K1  (88064 + 128)
#define OFF_K2  (88064 + 256)
#define OFF_TPV (88064 + 384)
#define OFF_PQ  0                      // overlay after MMA: 128*66 floats = 33792
#define PQ_STRIDE 66
#define SMEM_TOTAL 88576

__device__ __forceinline__ float fsig(float x) { return 1.0f / (1.0f + __expf(-x)); }

// ---------------- ptx helpers ----------------
__device__ __forceinline__ u32 smem_u32(const void* p) {
    u32 a;
    asm("{ .reg .u64 t; cvta.to.shared.u64 t, %1; cvt.u32.u64 %0, t; }" : "=r"(a) : "l"(p));
    return a;
}
__device__ __forceinline__ void ldm4(u32* r, u32 addr) {
    asm volatile("ldmatrix.sync.aligned.m8n8.x4.shared.b16 {%0,%1,%2,%3}, [%4];"
                 : "=r"(r[0]), "=r"(r[1]), "=r"(r[2]), "=r"(r[3]) : "r"(addr));
}
__device__ __forceinline__ void mma16816(float* d, const u32* a, const u32 b0, const u32 b1) {
    asm volatile(
        "mma.sync.aligned.m16n8k16.row.col.f32.bf16.bf16.f32 "
        "{%0,%1,%2,%3}, {%4,%5,%6,%7}, {%8,%9}, {%0,%1,%2,%3};"
        : "+f"(d[0]), "+f"(d[1]), "+f"(d[2]), "+f"(d[3])
        : "r"(a[0]), "r"(a[1]), "r"(a[2]), "r"(a[3]), "r"(b0), "r"(b1));
}

// ---------------- main kernel ----------------
__global__ __launch_bounds__(256, 2)
void hopf_kernel(const float* __restrict__ in,
                 const float* __restrict__ vv, const float* __restrict__ bb,
                 const float* __restrict__ cc, const float* __restrict__ ww,
                 const float* __restrict__ pp,
                 float* __restrict__ out, int nrows)
{
    extern __shared__ __align__(16) char smem[];
    u32 sb = smem_u32(smem);
    int tid = threadIdx.x;
    int lane = tid & 31;
    int wid = tid >> 5;

    // ---- per-CTA build: activation params + B coefficient tiles (in SMEM) ----
    if (tid < NOSC) {
        float va = 5.0f * fsig(vv[tid]);
        float ba = 2.0f * fsig(bb[tid]);
        float ca = 10.0f * fsig(cc[tid]);
        float K1 = 0.25f * ca * ca;
        ((float*)(smem + OFF_K0))[tid] = K1 * ba;
        ((float*)(smem + OFF_K1))[tid] = K1;
        ((float*)(smem + OFF_K2))[tid] = ca;
        ((float*)(smem + OFF_TPV))[tid] = TWO_PI * va;
    }
#pragma unroll
    for (int ei = 0; ei < 16; ei++) {
        int e = tid + 256 * ei;                    // 0..4095
        int n = e >> 6, k = e & 63;
        int j = k & 31;
        bool is_x = (k < 32);
        int i = n & 31;
        int flat = 32 * i + j;                     // index into zero-diag 32x32
        float A = 0.0f, Bc = 0.0f;
        if (flat != 1023) {
            // _zero_diag: z = concat([zeros(31,1), P],1).ravel() ++ [0] -> (32,32)
            int t = flat / 33, pos = flat % 33;
            if (pos != 0) {
                float wa = fsig(ww[t * 32 + pos - 1]);            // W_MAX = 1
                float pa = TWO_PI * fsig(pp[t * 32 + pos - 1]);
                float sp, cp;
                __sincosf(pa, &sp, &cp);
                A = wa * cp;
                Bc = wa * sp;
            }
        }
        float Mf;
        if (n < 32) Mf = is_x ? A : -Bc;     // P part
        else        Mf = is_x ? Bc : A;      // Q part
        __nv_bfloat16 hi = __float2bfloat16_rn(Mf);
        __nv_bfloat16 lo = __float2bfloat16_rn(Mf - __bfloat162float(hi));
        *(__nv_bfloat16*)(smem + OFF_BHI + n * B_STRIDE + k * 2) = hi;
        *(__nv_bfloat16*)(smem + OFF_BLO + n * B_STRIDE + k * 2) = lo;
    }
    __syncthreads();

    // ---- prologue: A tiles + cs cache + direct r_d / r_d_dot stores ----
    int base = blockIdx.x * TILE_ROWS;
    {
        int q = tid & 7;                           // j-quad, invariant
        float4 K0 = ((const float4*)(smem + OFF_K0))[q];
        float4 K1 = ((const float4*)(smem + OFF_K1))[q];
        float4 K2 = ((const float4*)(smem + OFF_K2))[q];
        float k0a[4] = {K0.x, K0.y, K0.z, K0.w};
        float k1a[4] = {K1.x, K1.y, K1.z, K1.w};
        float k2a[4] = {K2.x, K2.y, K2.z, K2.w};

#pragma unroll
        for (int it = 0; it < 4; it++) {
            int r = (tid >> 3) + 32 * it;          // row-in-tile
            int row = base + r;
            float4 p4 = make_float4(0.f, 0.f, 0.f, 0.f);
            float4 r4 = make_float4(0.f, 0.f, 0.f, 0.f);
            float4 d4 = make_float4(0.f, 0.f, 0.f, 0.f);
            if (row < nrows) {
                const float4* rp = (const float4*)(in + (size_t)row * 96);
                p4 = rp[q];
                r4 = rp[8 + q];
                d4 = rp[16 + q];
            }
            float px[4] = {p4.x, p4.y, p4.z, p4.w};
            float rx[4] = {r4.x, r4.y, r4.z, r4.w};
            float dx[4] = {d4.x, d4.y, d4.z, d4.w};
            float X[4], Y[4], S[4], C[4], F[4];
#pragma unroll
            for (int e = 0; e < 4; e++) {
                __sincosf(px[e], &S[e], &C[e]);
                X[e] = rx[e] * S[e];
                Y[e] = rx[e] * C[e];
                F[e] = fmaf(-k2a[e], dx[e], fmaf(-k1a[e], rx[e], k0a[e]));
            }
            u32 cso = OFF_CS + (u32)(r * 256 + q * 32);
            *(float4*)(smem + cso) = make_float4(C[0], S[0], C[1], S[1]);
            *(float4*)(smem + cso + 16) = make_float4(C[2], S[2], C[3], S[3]);

            __nv_bfloat162 xh01 = __floats2bfloat162_rn(X[0], X[1]);
            __nv_bfloat162 xh23 = __floats2bfloat162_rn(X[2], X[3]);
            __nv_bfloat162 yh01 = __floats2bfloat162_rn(Y[0], Y[1]);
            __nv_bfloat162 yh23 = __floats2bfloat162_rn(Y[2], Y[3]);
            __nv_bfloat162 xl01 = __floats2bfloat162_rn(X[0] - __bfloat162float(xh01.x),
                                                        X[1] - __bfloat162float(xh01.y));
            __nv_bfloat162 xl23 = __floats2bfloat162_rn(X[2] - __bfloat162float(xh23.x),
                                                        X[3] - __bfloat162float(xh23.y));
            __nv_bfloat162 yl01 = __floats2bfloat162_rn(Y[0] - __bfloat162float(yh01.x),
                                                        Y[1] - __bfloat162float(yh01.y));
            __nv_bfloat162 yl23 = __floats2bfloat162_rn(Y[2] - __bfloat162float(yh23.x),
                                                        Y[3] - __bfloat162float(yh23.y));
            u32 xo = r * A_STRIDE + q * 8;
            u32 yo = xo + 64;
            *(uint2*)(smem + OFF_AHI + xo) = make_uint2(*(u32*)&xh01, *(u32*)&xh23);
            *(uint2*)(smem + OFF_AHI + yo) = make_uint2(*(u32*)&yh01, *(u32*)&yh23);
            *(uint2*)(smem + OFF_ALO + xo) = make_uint2(*(u32*)&xl01, *(u32*)&xl23);
            *(uint2*)(smem + OFF_ALO + yo) = make_uint2(*(u32*)&yl01, *(u32*)&yl23);

            if (row < nrows) {
                float4* op = (float4*)(out + (size_t)row * 96);
                op[8 + q] = d4;                                   // r_d
                op[16 + q] = make_float4(F[0], F[1], F[2], F[3]); // r_d_dot
            }
        }
    }
    __syncthreads();

    // ---- MMA: warp owns 16 rows x 64 cols; Bhi loaded once per ks ----
    int mrow = wid * 16;
    float acc[8][4];
#pragma unroll
    for (int nt = 0; nt < 8; nt++)
#pragma unroll
        for (int e = 0; e < 4; e++) acc[nt][e] = 0.0f;

    int lrow = lane & 15;
    int lhalf = lane >> 4;

#pragma unroll
    for (int ks = 0; ks < 4; ks++) {
        u32 kb = ks * 32 + lhalf * 16;
        u32 ahi[4], alo[4];
        ldm4(ahi, sb + OFF_AHI + (u32)((mrow + lrow) * A_STRIDE) + kb);
        ldm4(alo, sb + OFF_ALO + (u32)((mrow + lrow) * A_STRIDE) + kb);
        u32 bh[4][4];
#pragma unroll
        for (int nb = 0; nb < 4; nb++)
            ldm4(bh[nb], sb + OFF_BHI + (u32)((nb * 16 + lrow) * B_STRIDE) + kb);
#pragma unroll
        for (int nb = 0; nb < 4; nb++) {
            mma16816(acc[2 * nb + 0], ahi, bh[nb][0], bh[nb][2]);
            mma16816(acc[2 * nb + 1], ahi, bh[nb][1], bh[nb][3]);
            mma16816(acc[2 * nb + 0], alo, bh[nb][0], bh[nb][2]);
            mma16816(acc[2 * nb + 1], alo, bh[nb][1], bh[nb][3]);
        }
        u32 bl[4][4];
#pragma unroll
        for (int nb = 0; nb < 4; nb++)
            ldm4(bl[nb], sb + OFF_BLO + (u32)((nb * 16 + lrow) * B_STRIDE) + kb);
#pragma unroll
        for (int nb = 0; nb < 4; nb++) {
            mma16816(acc[2 * nb + 0], ahi, bl[nb][0], bl[nb][2]);
            mma16816(acc[2 * nb + 1], ahi, bl[nb][1], bl[nb][3]);
        }
    }

    __syncthreads();   // all A reads done before PQ overlays the A region

    float* sPQ = (float*)(smem + OFF_PQ);
    {
        int g = lane >> 2;
        int tc = (lane & 3) * 2;
        int r0 = mrow + g;
#pragma unroll
        for (int nt = 0; nt < 8; nt++) {
            int col = nt * 8 + tc;
            *(float2*)(sPQ + r0 * PQ_STRIDE + col) = make_float2(acc[nt][0], acc[nt][1]);
            *(float2*)(sPQ + (r0 + 8) * PQ_STRIDE + col) = make_float2(acc[nt][2], acc[nt][3]);
        }
    }
    __syncthreads();

    // ---- epilogue: pure LDS + FMA + STG ----
    float tpv = ((const float*)(smem + OFF_TPV))[lane];
    const float2* sCS = (const float2*)(smem + OFF_CS);
#pragma unroll 4
    for (int rr = 0; rr < 16; rr++) {
        int rt = wid * 16 + rr;
        int row = base + rt;
        if (row < nrows) {
            float Pv = sPQ[rt * PQ_STRIDE + lane];
            float Qv = sPQ[rt * PQ_STRIDE + 32 + lane];
            float2 cs = sCS[rt * 32 + lane];       // (cos, sin)
            float psidot = fmaf(cs.x, Pv, fmaf(-cs.y, Qv, tpv));
            out[(size_t)row * 96 + lane] = psidot;
        }
    }
}

extern "C" void kernel_launch(void* const* d_in, const int* in_sizes, int n_in,
                              void* d_out, int out_size)
{
    const float* states = (const float*)d_in[0];
    const float* v = (const float*)d_in[1];
    const float* b = (const float*)d_in[2];
    const float* c = (const float*)d_in[3];
    const float* w = (const float*)d_in[4];
    const float* phi = (const float*)d_in[5];
    int nrows = in_sizes[0] / 96;

    cudaFuncSetAttribute(hopf_kernel, cudaFuncAttributeMaxDynamicSharedMemorySize,
                         SMEM_TOTAL);

    int grid = (nrows + TILE_ROWS - 1) / TILE_ROWS;
    hopf_kernel<<<grid, 256, SMEM_TOTAL>>>(states, v, b, c, w, phi, (float*)d_out, nrows);
}

// round 11
// speedup vs baseline: 1.3521x; 1.3521x over previous
#include <cuda_runtime.h>
#include <cuda_bf16.h>
#include <cstdint>

// HopfOscillatorModule, round 10 (re-bench of R9; prior run died on infra):
// R7 structure (separate setup kernel) + Bhi-reuse MMA ordering + occupancy:
//  - psi cached in SMEM (16KB) instead of (cos,sin) (32KB); epilogue recomputes
//    sincos (cheap MUFU) -> SMEM 71.7KB -> 3 CTAs/SM.
//  - __launch_bounds__(256,3): 24 warps/SM, waves 512/444 = 1.15.
//   [P|Q](row) = [x|y](row) . M,  M 64x64 constant (from setup kernel).
//   psi_dot_i = 2*pi*v_i + cos(psi_i)*P_i - sin(psi_i)*Q_i

#define NOSC 32
#define TILE_ROWS 128
#define TWO_PI 6.283185307179586f

typedef unsigned int u32;

#define A_STRIDE 144
#define B_STRIDE 144
#define OFF_AHI 0                      // 128*144 = 18432
#define OFF_ALO 18432                  // -> 36864
#define OFF_BHI 36864                  // 64*144 = 9216 -> 46080
#define OFF_BLO 46080                  // -> 55296
#define OFF_PSI 55296                  // float[128][32] = 16384 -> 71680
#define OFF_PQ  0                      // overlay after MMA: 128*66 floats = 33792
#define PQ_STRIDE 66
#define SMEM_TOTAL 71680

__device__ __align__(16) unsigned char g_Bhi[64 * B_STRIDE];
__device__ __align__(16) unsigned char g_Blo[64 * B_STRIDE];
__device__ __align__(16) float g_K0[NOSC];
__device__ __align__(16) float g_K1[NOSC];
__device__ __align__(16) float g_K2[NOSC];
__device__ __align__(16) float g_tpv[NOSC];

__device__ __forceinline__ float sigmoidf_(float x) { return 1.0f / (1.0f + expf(-x)); }

// ---------------- setup (one tiny launch; off the hot path) ----------------
__global__ void hopf_setup_kernel(const float* __restrict__ v, const float* __restrict__ b,
                                  const float* __restrict__ c, const float* __restrict__ w,
                                  const float* __restrict__ phi)
{
    int tid = threadIdx.x;
    if (tid < NOSC) {
        float va = 5.0f * sigmoidf_(v[tid]);
        float ba = 2.0f * sigmoidf_(b[tid]);
        float ca = 10.0f * sigmoidf_(c[tid]);
        float K1 = 0.25f * ca * ca;
        g_K0[tid] = K1 * ba;
        g_K1[tid] = K1;
        g_K2[tid] = ca;
        g_tpv[tid] = TWO_PI * va;
    }
    for (int e = tid; e < 64 * 64; e += blockDim.x) {
        int n = e >> 6, k = e & 63;
        int j = k & 31;
        bool is_x = (k < 32);
        int i = n & 31;
        int flat = 32 * i + j;                     // index into zero-diag 32x32
        float A = 0.0f, Bc = 0.0f;
        if (flat != 1023) {
            // _zero_diag: z = concat([zeros(31,1), P],1).ravel() ++ [0] -> (32,32)
            int t = flat / 33, pos = flat % 33;
            if (pos != 0) {
                float wa = sigmoidf_(w[t * 32 + pos - 1]);            // W_MAX = 1
                float pa = TWO_PI * sigmoidf_(phi[t * 32 + pos - 1]);
                float sp, cp;
                sincosf(pa, &sp, &cp);
                A = wa * cp;
                Bc = wa * sp;
            }
        }
        float Mf;
        if (n < 32) Mf = is_x ? A : -Bc;     // P part
        else        Mf = is_x ? Bc : A;      // Q part
        __nv_bfloat16 hi = __float2bfloat16_rn(Mf);
        __nv_bfloat16 lo = __float2bfloat16_rn(Mf - __bfloat162float(hi));
        *(__nv_bfloat16*)(g_Bhi + n * B_STRIDE + k * 2) = hi;
        *(__nv_bfloat16*)(g_Blo + n * B_STRIDE + k * 2) = lo;
    }
}

// ---------------- ptx helpers ----------------
__device__ __forceinline__ u32 smem_u32(const void* p) {
    u32 a;
    asm("{ .reg .u64 t; cvta.to.shared.u64 t, %1; cvt.u32.u64 %0, t; }" : "=r"(a) : "l"(p));
    return a;
}
__device__ __forceinline__ void ldm4(u32* r, u32 addr) {
    asm volatile("ldmatrix.sync.aligned.m8n8.x4.shared.b16 {%0,%1,%2,%3}, [%4];"
                 : "=r"(r[0]), "=r"(r[1]), "=r"(r[2]), "=r"(r[3]) : "r"(addr));
}
__device__ __forceinline__ void mma16816(float* d, const u32* a, const u32 b0, const u32 b1) {
    asm volatile(
        "mma.sync.aligned.m16n8k16.row.col.f32.bf16.bf16.f32 "
        "{%0,%1,%2,%3}, {%4,%5,%6,%7}, {%8,%9}, {%0,%1,%2,%3};"
        : "+f"(d[0]), "+f"(d[1]), "+f"(d[2]), "+f"(d[3])
        : "r"(a[0]), "r"(a[1]), "r"(a[2]), "r"(a[3]), "r"(b0), "r"(b1));
}

// ---------------- main kernel ----------------
__global__ __launch_bounds__(256, 3)
void hopf_kernel(const float* __restrict__ in, float* __restrict__ out, int nrows)
{
    extern __shared__ __align__(16) char smem[];
    u32 sb = smem_u32(smem);
    int tid = threadIdx.x;
    int lane = tid & 31;
    int wid = tid >> 5;

    // Stage constant B tiles into SMEM.
    {
        const uint4* gh = (const uint4*)g_Bhi;
        const uint4* gl = (const uint4*)g_Blo;
        uint4* sh = (uint4*)(smem + OFF_BHI);
        uint4* sl = (uint4*)(smem + OFF_BLO);
        for (int i = tid; i < (64 * B_STRIDE) / 16; i += 256) {
            sh[i] = gh[i];
            sl[i] = gl[i];
        }
    }

    // ---- prologue: A tiles + psi cache + direct r_d / r_d_dot stores ----
    int base = blockIdx.x * TILE_ROWS;
    {
        int q = tid & 7;                           // j-quad, invariant per thread
        float4 K0 = ((const float4*)g_K0)[q];
        float4 K1 = ((const float4*)g_K1)[q];
        float4 K2 = ((const float4*)g_K2)[q];
        float k0a[4] = {K0.x, K0.y, K0.z, K0.w};
        float k1a[4] = {K1.x, K1.y, K1.z, K1.w};
        float k2a[4] = {K2.x, K2.y, K2.z, K2.w};

#pragma unroll
        for (int it = 0; it < 4; it++) {
            int r = (tid >> 3) + 32 * it;          // row-in-tile
            int row = base + r;
            float4 p4 = make_float4(0.f, 0.f, 0.f, 0.f);
            float4 r4 = make_float4(0.f, 0.f, 0.f, 0.f);
            float4 d4 = make_float4(0.f, 0.f, 0.f, 0.f);
            if (row < nrows) {
                const float4* rp = (const float4*)(in + (size_t)row * 96);
                p4 = rp[q];
                r4 = rp[8 + q];
                d4 = rp[16 + q];
            }
            float px[4] = {p4.x, p4.y, p4.z, p4.w};
            float rx[4] = {r4.x, r4.y, r4.z, r4.w};
            float dx[4] = {d4.x, d4.y, d4.z, d4.w};
            float X[4], Y[4], F[4];
#pragma unroll
            for (int e = 0; e < 4; e++) {
                float s, c;
                __sincosf(px[e], &s, &c);
                X[e] = rx[e] * s;
                Y[e] = rx[e] * c;
                F[e] = fmaf(-k2a[e], dx[e], fmaf(-k1a[e], rx[e], k0a[e]));
            }
            // psi cache for the epilogue (recompute sincos there).
            *(float4*)(smem + OFF_PSI + (u32)(r * 128 + q * 16)) = p4;

            __nv_bfloat162 xh01 = __floats2bfloat162_rn(X[0], X[1]);
            __nv_bfloat162 xh23 = __floats2bfloat162_rn(X[2], X[3]);
            __nv_bfloat162 yh01 = __floats2bfloat162_rn(Y[0], Y[1]);
            __nv_bfloat162 yh23 = __floats2bfloat162_rn(Y[2], Y[3]);
            __nv_bfloat162 xl01 = __floats2bfloat162_rn(X[0] - __bfloat162float(xh01.x),
                                                        X[1] - __bfloat162float(xh01.y));
            __nv_bfloat162 xl23 = __floats2bfloat162_rn(X[2] - __bfloat162float(xh23.x),
                                                        X[3] - __bfloat162float(xh23.y));
            __nv_bfloat162 yl01 = __floats2bfloat162_rn(Y[0] - __bfloat162float(yh01.x),
                                                        Y[1] - __bfloat162float(yh01.y));
            __nv_bfloat162 yl23 = __floats2bfloat162_rn(Y[2] - __bfloat162float(yh23.x),
                                                        Y[3] - __bfloat162float(yh23.y));
            u32 xo = r * A_STRIDE + q * 8;
            u32 yo = xo + 64;
            *(uint2*)(smem + OFF_AHI + xo) = make_uint2(*(u32*)&xh01, *(u32*)&xh23);
            *(uint2*)(smem + OFF_AHI + yo) = make_uint2(*(u32*)&yh01, *(u32*)&yh23);
            *(uint2*)(smem + OFF_ALO + xo) = make_uint2(*(u32*)&xl01, *(u32*)&xl23);
            *(uint2*)(smem + OFF_ALO + yo) = make_uint2(*(u32*)&yl01, *(u32*)&yl23);

            if (row < nrows) {
                float4* op = (float4*)(out + (size_t)row * 96);
                op[8 + q] = d4;                                   // r_d
                op[16 + q] = make_float4(F[0], F[1], F[2], F[3]); // r_d_dot
            }
        }
    }
    __syncthreads();

    // ---- MMA: warp owns 16 rows x 64 cols; Bhi fragments loaded once per ks ----
    int mrow = wid * 16;
    float acc[8][4];
#pragma unroll
    for (int nt = 0; nt < 8; nt++)
#pragma unroll
        for (int e = 0; e < 4; e++) acc[nt][e] = 0.0f;

    int lrow = lane & 15;
    int lhalf = lane >> 4;

#pragma unroll
    for (int ks = 0; ks < 4; ks++) {
        u32 kb = ks * 32 + lhalf * 16;
        u32 ahi[4], alo[4];
        ldm4(ahi, sb + OFF_AHI + (u32)((mrow + lrow) * A_STRIDE) + kb);
        ldm4(alo, sb + OFF_ALO + (u32)((mrow + lrow) * A_STRIDE) + kb);
        u32 bh[4][4];
#pragma unroll
        for (int nb = 0; nb < 4; nb++)
            ldm4(bh[nb], sb + OFF_BHI + (u32)((nb * 16 + lrow) * B_STRIDE) + kb);
#pragma unroll
        for (int nb = 0; nb < 4; nb++) {
            mma16816(acc[2 * nb + 0], ahi, bh[nb][0], bh[nb][2]);
            mma16816(acc[2 * nb + 1], ahi, bh[nb][1], bh[nb][3]);
            mma16816(acc[2 * nb + 0], alo, bh[nb][0], bh[nb][2]);
            mma16816(acc[2 * nb + 1], alo, bh[nb][1], bh[nb][3]);
        }
        u32 bl[4][4];
#pragma unroll
        for (int nb = 0; nb < 4; nb++)
            ldm4(bl[nb], sb + OFF_BLO + (u32)((nb * 16 + lrow) * B_STRIDE) + kb);
#pragma unroll
        for (int nb = 0; nb < 4; nb++) {
            mma16816(acc[2 * nb + 0], ahi, bl[nb][0], bl[nb][2]);
            mma16816(acc[2 * nb + 1], ahi, bl[nb][1], bl[nb][3]);
        }
    }

    __syncthreads();   // all A reads done before PQ overlays the A region

    float* sPQ = (float*)(smem + OFF_PQ);
    {
        int g = lane >> 2;
        int tc = (lane & 3) * 2;
        int r0 = mrow + g;
#pragma unroll
        for (int nt = 0; nt < 8; nt++) {
            int col = nt * 8 + tc;
            *(float2*)(sPQ + r0 * PQ_STRIDE + col) = make_float2(acc[nt][0], acc[nt][1]);
            *(float2*)(sPQ + (r0 + 8) * PQ_STRIDE + col) = make_float2(acc[nt][2], acc[nt][3]);
        }
    }
    __syncthreads();

    // ---- epilogue: LDS psi + sincos + FMA + STG ----
    float tpv = __ldg(&g_tpv[lane]);
    const float* sPSI = (const float*)(smem + OFF_PSI);
#pragma unroll 4
    for (int rr = 0; rr < 16; rr++) {
        int rt = wid * 16 + rr;
        int row = base + rt;
        if (row < nrows) {
            float Pv = sPQ[rt * PQ_STRIDE + lane];
            float Qv = sPQ[rt * PQ_STRIDE + 32 + lane];
            float psi = sPSI[rt * 32 + lane];
            float s, c;
            __sincosf(psi, &s, &c);
            float psidot = fmaf(c, Pv, fmaf(-s, Qv, tpv));
            out[(size_t)row * 96 + lane] = psidot;
        }
    }
}

extern "C" void kernel_launch(void* const* d_in, const int* in_sizes, int n_in,
                              void* d_out, int out_size)
{
    const float* states = (const float*)d_in[0];
    const float* v = (const float*)d_in[1];
    const float* b = (const float*)d_in[2];
    const float* c = (const float*)d_in[3];
    const float* w = (const float*)d_in[4];
    const float* phi = (const float*)d_in[5];
    int nrows = in_sizes[0] / 96;

    cudaFuncSetAttribute(hopf_kernel, cudaFuncAttributeMaxDynamicSharedMemorySize,
                         SMEM_TOTAL);

    hopf_setup_kernel<<<1, 1024>>>(v, b, c, w, phi);

    int grid = (nrows + TILE_ROWS - 1) / TILE_ROWS;
    hopf_kernel<<<grid, 256, SMEM_TOTAL>>>(states, (float*)d_out, nrows);
}

// round 12
// speedup vs baseline: 1.6661x; 1.2322x over previous
#include <cuda_runtime.h>
#include <cuda_bf16.h>
#include <cstdint>

// HopfOscillatorModule, round 12: register-fused epilogue.
//   [P|Q](row) = [x|y](row) . M (64x64 const, bf16 3-term split, HMMA).
//   psi_dot computed directly from MMA fragments (P_i and Q_i=col 32+i land in
//   the SAME thread's registers) -> no PQ SMEM staging, no post-MMA barriers.
//   psi cached in SMEM (stride 144B) for the epilogue sincos.
// Setup kernel parallelized to 32 CTAs.

#define NOSC 32
#define TILE_ROWS 128
#define TWO_PI 6.283185307179586f

typedef unsigned int u32;

#define A_STRIDE 144
#define B_STRIDE 144
#define PSI_STRIDE 144                 // bytes; 36 floats: 16B-aligned, low-conflict
#define OFF_AHI 0                      // 128*144 = 18432
#define OFF_ALO 18432                  // -> 36864
#define OFF_BHI 36864                  // 64*144 = 9216 -> 46080
#define OFF_BLO 46080                  // -> 55296
#define OFF_PSI 55296                  // 128*144 = 18432 -> 73728
#define OFF_TPV 73728                  // 128 -> 73856
#define SMEM_TOTAL 73856

__device__ __align__(16) unsigned char g_Bhi[64 * B_STRIDE];
__device__ __align__(16) unsigned char g_Blo[64 * B_STRIDE];
__device__ __align__(16) float g_K0[NOSC];
__device__ __align__(16) float g_K1[NOSC];
__device__ __align__(16) float g_K2[NOSC];
__device__ __align__(16) float g_tpv[NOSC];

__device__ __forceinline__ float sigmoidf_(float x) { return 1.0f / (1.0f + expf(-x)); }

// ---------------- setup: 32 CTAs, one B-entry per thread ----------------
__global__ void hopf_setup_kernel(const float* __restrict__ v, const float* __restrict__ b,
                                  const float* __restrict__ c, const float* __restrict__ w,
                                  const float* __restrict__ phi)
{
    int tid = threadIdx.x;
    if (blockIdx.x == 0 && tid < NOSC) {
        float va = 5.0f * sigmoidf_(v[tid]);
        float ba = 2.0f * sigmoidf_(b[tid]);
        float ca = 10.0f * sigmoidf_(c[tid]);
        float K1 = 0.25f * ca * ca;
        g_K0[tid] = K1 * ba;
        g_K1[tid] = K1;
        g_K2[tid] = ca;
        g_tpv[tid] = TWO_PI * va;
    }
    int e = blockIdx.x * 128 + tid;            // 0..4095
    int n = e >> 6, k = e & 63;
    int j = k & 31;
    bool is_x = (k < 32);
    int i = n & 31;
    int flat = 32 * i + j;                     // index into zero-diag 32x32
    float A = 0.0f, Bc = 0.0f;
    if (flat != 1023) {
        // _zero_diag: z = concat([zeros(31,1), P],1).ravel() ++ [0] -> (32,32)
        int t = flat / 33, pos = flat % 33;
        if (pos != 0) {
            float wa = sigmoidf_(w[t * 32 + pos - 1]);            // W_MAX = 1
            float pa = TWO_PI * sigmoidf_(phi[t * 32 + pos - 1]);
            float sp, cp;
            sincosf(pa, &sp, &cp);
            A = wa * cp;
            Bc = wa * sp;
        }
    }
    float Mf;
    if (n < 32) Mf = is_x ? A : -Bc;     // P part
    else        Mf = is_x ? Bc : A;      // Q part
    __nv_bfloat16 hi = __float2bfloat16_rn(Mf);
    __nv_bfloat16 lo = __float2bfloat16_rn(Mf - __bfloat162float(hi));
    *(__nv_bfloat16*)(g_Bhi + n * B_STRIDE + k * 2) = hi;
    *(__nv_bfloat16*)(g_Blo + n * B_STRIDE + k * 2) = lo;
}

// ---------------- ptx helpers ----------------
__device__ __forceinline__ u32 smem_u32(const void* p) {
    u32 a;
    asm("{ .reg .u64 t; cvta.to.shared.u64 t, %1; cvt.u32.u64 %0, t; }" : "=r"(a) : "l"(p));
    return a;
}
__device__ __forceinline__ void ldm4(u32* r, u32 addr) {
    asm volatile("ldmatrix.sync.aligned.m8n8.x4.shared.b16 {%0,%1,%2,%3}, [%4];"
                 : "=r"(r[0]), "=r"(r[1]), "=r"(r[2]), "=r"(r[3]) : "r"(addr));
}
__device__ __forceinline__ void mma16816(float* d, const u32* a, const u32 b0, const u32 b1) {
    asm volatile(
        "mma.sync.aligned.m16n8k16.row.col.f32.bf16.bf16.f32 "
        "{%0,%1,%2,%3}, {%4,%5,%6,%7}, {%8,%9}, {%0,%1,%2,%3};"
        : "+f"(d[0]), "+f"(d[1]), "+f"(d[2]), "+f"(d[3])
        : "r"(a[0]), "r"(a[1]), "r"(a[2]), "r"(a[3]), "r"(b0), "r"(b1));
}

// ---------------- main kernel ----------------
__global__ __launch_bounds__(256, 3)
void hopf_kernel(const float* __restrict__ in, float* __restrict__ out, int nrows)
{
    extern __shared__ __align__(16) char smem[];
    u32 sb = smem_u32(smem);
    int tid = threadIdx.x;
    int lane = tid & 31;
    int wid = tid >> 5;

    // Stage constant B tiles + tpv into SMEM.
    {
        const uint4* gh = (const uint4*)g_Bhi;
        const uint4* gl = (const uint4*)g_Blo;
        uint4* sh = (uint4*)(smem + OFF_BHI);
        uint4* sl = (uint4*)(smem + OFF_BLO);
        for (int i = tid; i < (64 * B_STRIDE) / 16; i += 256) {
            sh[i] = gh[i];
            sl[i] = gl[i];
        }
        if (tid < NOSC) ((float*)(smem + OFF_TPV))[tid] = g_tpv[tid];
    }

    // ---- prologue: A tiles + psi cache + direct r_d / r_d_dot stores ----
    int base = blockIdx.x * TILE_ROWS;
    {
        int q = tid & 7;                           // j-quad, invariant per thread
        float4 K0 = ((const float4*)g_K0)[q];
        float4 K1 = ((const float4*)g_K1)[q];
        float4 K2 = ((const float4*)g_K2)[q];
        float k0a[4] = {K0.x, K0.y, K0.z, K0.w};
        float k1a[4] = {K1.x, K1.y, K1.z, K1.w};
        float k2a[4] = {K2.x, K2.y, K2.z, K2.w};

#pragma unroll
        for (int it = 0; it < 4; it++) {
            int r = (tid >> 3) + 32 * it;          // row-in-tile
            int row = base + r;
            float4 p4 = make_float4(0.f, 0.f, 0.f, 0.f);
            float4 r4 = make_float4(0.f, 0.f, 0.f, 0.f);
            float4 d4 = make_float4(0.f, 0.f, 0.f, 0.f);
            if (row < nrows) {
                const float4* rp = (const float4*)(in + (size_t)row * 96);
                p4 = rp[q];
                r4 = rp[8 + q];
                d4 = rp[16 + q];
            }
            float px[4] = {p4.x, p4.y, p4.z, p4.w};
            float rx[4] = {r4.x, r4.y, r4.z, r4.w};
            float dx[4] = {d4.x, d4.y, d4.z, d4.w};
            float X[4], Y[4], F[4];
#pragma unroll
            for (int e = 0; e < 4; e++) {
                float s, c;
                __sincosf(px[e], &s, &c);
                X[e] = rx[e] * s;
                Y[e] = rx[e] * c;
                F[e] = fmaf(-k2a[e], dx[e], fmaf(-k1a[e], rx[e], k0a[e]));
            }
            // psi cache for the register-fused epilogue.
            *(float4*)(smem + OFF_PSI + (u32)(r * PSI_STRIDE + q * 16)) = p4;

            __nv_bfloat162 xh01 = __floats2bfloat162_rn(X[0], X[1]);
            __nv_bfloat162 xh23 = __floats2bfloat162_rn(X[2], X[3]);
            __nv_bfloat162 yh01 = __floats2bfloat162_rn(Y[0], Y[1]);
            __nv_bfloat162 yh23 = __floats2bfloat162_rn(Y[2], Y[3]);
            __nv_bfloat162 xl01 = __floats2bfloat162_rn(X[0] - __bfloat162float(xh01.x),
                                                        X[1] - __bfloat162float(xh01.y));
            __nv_bfloat162 xl23 = __floats2bfloat162_rn(X[2] - __bfloat162float(xh23.x),
                                                        X[3] - __bfloat162float(xh23.y));
            __nv_bfloat162 yl01 = __floats2bfloat162_rn(Y[0] - __bfloat162float(yh01.x),
                                                        Y[1] - __bfloat162float(yh01.y));
            __nv_bfloat162 yl23 = __floats2bfloat162_rn(Y[2] - __bfloat162float(yh23.x),
                                                        Y[3] - __bfloat162float(yh23.y));
            u32 xo = r * A_STRIDE + q * 8;
            u32 yo = xo + 64;
            *(uint2*)(smem + OFF_AHI + xo) = make_uint2(*(u32*)&xh01, *(u32*)&xh23);
            *(uint2*)(smem + OFF_AHI + yo) = make_uint2(*(u32*)&yh01, *(u32*)&yh23);
            *(uint2*)(smem + OFF_ALO + xo) = make_uint2(*(u32*)&xl01, *(u32*)&xl23);
            *(uint2*)(smem + OFF_ALO + yo) = make_uint2(*(u32*)&yl01, *(u32*)&yl23);

            if (row < nrows) {
                float4* op = (float4*)(out + (size_t)row * 96);
                op[8 + q] = d4;                                   // r_d
                op[16 + q] = make_float4(F[0], F[1], F[2], F[3]); // r_d_dot
            }
        }
    }
    __syncthreads();   // the ONLY barrier: A/psi/B tiles ready

    // ---- MMA: warp owns 16 rows x 64 cols; Bhi fragments loaded once per ks ----
    int mrow = wid * 16;
    float acc[8][4];
#pragma unroll
    for (int nt = 0; nt < 8; nt++)
#pragma unroll
        for (int e = 0; e < 4; e++) acc[nt][e] = 0.0f;

    int lrow = lane & 15;
    int lhalf = lane >> 4;

#pragma unroll
    for (int ks = 0; ks < 4; ks++) {
        u32 kb = ks * 32 + lhalf * 16;
        u32 ahi[4], alo[4];
        ldm4(ahi, sb + OFF_AHI + (u32)((mrow + lrow) * A_STRIDE) + kb);
        ldm4(alo, sb + OFF_ALO + (u32)((mrow + lrow) * A_STRIDE) + kb);
        u32 bh[4][4];
#pragma unroll
        for (int nb = 0; nb < 4; nb++)
            ldm4(bh[nb], sb + OFF_BHI + (u32)((nb * 16 + lrow) * B_STRIDE) + kb);
#pragma unroll
        for (int nb = 0; nb < 4; nb++) {
            mma16816(acc[2 * nb + 0], ahi, bh[nb][0], bh[nb][2]);
            mma16816(acc[2 * nb + 1], ahi, bh[nb][1], bh[nb][3]);
            mma16816(acc[2 * nb + 0], alo, bh[nb][0], bh[nb][2]);
            mma16816(acc[2 * nb + 1], alo, bh[nb][1], bh[nb][3]);
        }
        u32 bl[4][4];
#pragma unroll
        for (int nb = 0; nb < 4; nb++)
            ldm4(bl[nb], sb + OFF_BLO + (u32)((nb * 16 + lrow) * B_STRIDE) + kb);
#pragma unroll
        for (int nb = 0; nb < 4; nb++) {
            mma16816(acc[2 * nb + 0], ahi, bl[nb][0], bl[nb][2]);
            mma16816(acc[2 * nb + 1], ahi, bl[nb][1], bl[nb][3]);
        }
    }

    // ---- register-fused epilogue: fragment (row,col) -> psi_dot -> STG.64 ----
    // Fragment layout: acc[nt][0..1] = row mrow+g, cols nt*8+tc+{0,1};
    //                  acc[nt][2..3] = row mrow+g+8. nt<4 => P, nt>=4 => Q(col-32).
    {
        int g = lane >> 2;
        int tc = (lane & 3) * 2;
        int r0 = mrow + g;
        int row0 = base + r0;
        int row1 = row0 + 8;
#pragma unroll
        for (int cp = 0; cp < 4; cp++) {
            int col = cp * 8 + tc;
            float2 tp = *(const float2*)(smem + OFF_TPV + col * 4);
            float2 ps0 = *(const float2*)(smem + OFF_PSI + (u32)(r0 * PSI_STRIDE + col * 4));
            float2 ps1 = *(const float2*)(smem + OFF_PSI + (u32)((r0 + 8) * PSI_STRIDE + col * 4));
            float s, c;
            __sincosf(ps0.x, &s, &c);
            float v0 = fmaf(c, acc[cp][0], fmaf(-s, acc[cp + 4][0], tp.x));
            __sincosf(ps0.y, &s, &c);
            float v1 = fmaf(c, acc[cp][1], fmaf(-s, acc[cp + 4][1], tp.y));
            __sincosf(ps1.x, &s, &c);
            float w0 = fmaf(c, acc[cp][2], fmaf(-s, acc[cp + 4][2], tp.x));
            __sincosf(ps1.y, &s, &c);
            float w1 = fmaf(c, acc[cp][3], fmaf(-s, acc[cp + 4][3], tp.y));
            if (row0 < nrows)
                *(float2*)(out + (size_t)row0 * 96 + col) = make_float2(v0, v1);
            if (row1 < nrows)
                *(float2*)(out + (size_t)row1 * 96 + col) = make_float2(w0, w1);
        }
    }
}

extern "C" void kernel_launch(void* const* d_in, const int* in_sizes, int n_in,
                              void* d_out, int out_size)
{
    const float* states = (const float*)d_in[0];
    const float* v = (const float*)d_in[1];
    const float* b = (const float*)d_in[2];
    const float* c = (const float*)d_in[3];
    const float* w = (const float*)d_in[4];
    const float* phi = (const float*)d_in[5];
    int nrows = in_sizes[0] / 96;

    cudaFuncSetAttribute(hopf_kernel, cudaFuncAttributeMaxDynamicSharedMemorySize,
                         SMEM_TOTAL);

    hopf_setup_kernel<<<32, 128>>>(v, b, c, w, phi);

    int grid = (nrows + TILE_ROWS - 1) / TILE_ROWS;
    hopf_kernel<<<grid, 256, SMEM_TOTAL>>>(states, (float*)d_out, nrows);
}

// round 13
// speedup vs baseline: 1.7306x; 1.0387x over previous
#include <cuda_runtime.h>
#include <cuda_bf16.h>
#include <cstdint>

// HopfOscillatorModule, round 13: fully warp-decoupled phases.
//   [P|Q](row) = [x|y](row) . M (64x64 const, bf16 3-term split, HMMA).
//   Warp w owns rows [16w,16w+16): it writes their A-tile/psi entries itself
//   (same coalescing as before), so after ONE early __syncthreads (guarding
//   only the B tiles), each warp runs prologue -> syncwarp -> MMA -> fused
//   epilogue with no cross-warp barrier at all.

#define NOSC 32
#define TILE_ROWS 128
#define TWO_PI 6.283185307179586f

typedef unsigned int u32;

#define A_STRIDE 144
#define B_STRIDE 144
#define PSI_STRIDE 144                 // bytes
#define OFF_AHI 0                      // 128*144 = 18432
#define OFF_ALO 18432                  // -> 36864
#define OFF_BHI 36864                  // 64*144 = 9216 -> 46080
#define OFF_BLO 46080                  // -> 55296
#define OFF_PSI 55296                  // 128*144 = 18432 -> 73728
#define OFF_TPV 73728                  // 128 -> 73856
#define SMEM_TOTAL 73856

__device__ __align__(16) unsigned char g_Bhi[64 * B_STRIDE];
__device__ __align__(16) unsigned char g_Blo[64 * B_STRIDE];
__device__ __align__(16) float g_K0[NOSC];
__device__ __align__(16) float g_K1[NOSC];
__device__ __align__(16) float g_K2[NOSC];
__device__ __align__(16) float g_tpv[NOSC];

__device__ __forceinline__ float sigmoidf_(float x) { return 1.0f / (1.0f + expf(-x)); }

// ---------------- setup: 32 CTAs, one B-entry per thread ----------------
__global__ void hopf_setup_kernel(const float* __restrict__ v, const float* __restrict__ b,
                                  const float* __restrict__ c, const float* __restrict__ w,
                                  const float* __restrict__ phi)
{
    int tid = threadIdx.x;
    if (blockIdx.x == 0 && tid < NOSC) {
        float va = 5.0f * sigmoidf_(v[tid]);
        float ba = 2.0f * sigmoidf_(b[tid]);
        float ca = 10.0f * sigmoidf_(c[tid]);
        float K1 = 0.25f * ca * ca;
        g_K0[tid] = K1 * ba;
        g_K1[tid] = K1;
        g_K2[tid] = ca;
        g_tpv[tid] = TWO_PI * va;
    }
    int e = blockIdx.x * 128 + tid;            // 0..4095
    int n = e >> 6, k = e & 63;
    int j = k & 31;
    bool is_x = (k < 32);
    int i = n & 31;
    int flat = 32 * i + j;                     // index into zero-diag 32x32
    float A = 0.0f, Bc = 0.0f;
    if (flat != 1023) {
        // _zero_diag: z = concat([zeros(31,1), P],1).ravel() ++ [0] -> (32,32)
        int t = flat / 33, pos = flat % 33;
        if (pos != 0) {
            float wa = sigmoidf_(w[t * 32 + pos - 1]);            // W_MAX = 1
            float pa = TWO_PI * sigmoidf_(phi[t * 32 + pos - 1]);
            float sp, cp;
            sincosf(pa, &sp, &cp);
            A = wa * cp;
            Bc = wa * sp;
        }
    }
    float Mf;
    if (n < 32) Mf = is_x ? A : -Bc;     // P part
    else        Mf = is_x ? Bc : A;      // Q part
    __nv_bfloat16 hi = __float2bfloat16_rn(Mf);
    __nv_bfloat16 lo = __float2bfloat16_rn(Mf - __bfloat162float(hi));
    *(__nv_bfloat16*)(g_Bhi + n * B_STRIDE + k * 2) = hi;
    *(__nv_bfloat16*)(g_Blo + n * B_STRIDE + k * 2) = lo;
}

// ---------------- ptx helpers ----------------
__device__ __forceinline__ u32 smem_u32(const void* p) {
    u32 a;
    asm("{ .reg .u64 t; cvta.to.shared.u64 t, %1; cvt.u32.u64 %0, t; }" : "=r"(a) : "l"(p));
    return a;
}
__device__ __forceinline__ void ldm4(u32* r, u32 addr) {
    asm volatile("ldmatrix.sync.aligned.m8n8.x4.shared.b16 {%0,%1,%2,%3}, [%4];"
                 : "=r"(r[0]), "=r"(r[1]), "=r"(r[2]), "=r"(r[3]) : "r"(addr));
}
__device__ __forceinline__ void mma16816(float* d, const u32* a, const u32 b0, const u32 b1) {
    asm volatile(
        "mma.sync.aligned.m16n8k16.row.col.f32.bf16.bf16.f32 "
        "{%0,%1,%2,%3}, {%4,%5,%6,%7}, {%8,%9}, {%0,%1,%2,%3};"
        : "+f"(d[0]), "+f"(d[1]), "+f"(d[2]), "+f"(d[3])
        : "r"(a[0]), "r"(a[1]), "r"(a[2]), "r"(a[3]), "r"(b0), "r"(b1));
}

// ---------------- main kernel ----------------
__global__ __launch_bounds__(256, 3)
void hopf_kernel(const float* __restrict__ in, float* __restrict__ out, int nrows)
{
    extern __shared__ __align__(16) char smem[];
    u32 sb = smem_u32(smem);
    int tid = threadIdx.x;
    int lane = tid & 31;
    int wid = tid >> 5;

    // Stage constant B tiles + tpv into SMEM, guarded by ONE early barrier.
    {
        const uint4* gh = (const uint4*)g_Bhi;
        const uint4* gl = (const uint4*)g_Blo;
        uint4* sh = (uint4*)(smem + OFF_BHI);
        uint4* sl = (uint4*)(smem + OFF_BLO);
        for (int i = tid; i < (64 * B_STRIDE) / 16; i += 256) {
            sh[i] = gh[i];
            sl[i] = gl[i];
        }
        if (tid < NOSC) ((float*)(smem + OFF_TPV))[tid] = g_tpv[tid];
    }
    __syncthreads();   // the ONLY block-wide barrier (B tiles + tpv ready)

    // ---- warp-local prologue: warp w builds A/psi rows [16w, 16w+16) ----
    int base = blockIdx.x * TILE_ROWS;
    int mrow = wid * 16;
    {
        int q = lane & 7;                          // j-quad, invariant per thread
        float4 K0 = ((const float4*)g_K0)[q];
        float4 K1 = ((const float4*)g_K1)[q];
        float4 K2 = ((const float4*)g_K2)[q];
        float k0a[4] = {K0.x, K0.y, K0.z, K0.w};
        float k1a[4] = {K1.x, K1.y, K1.z, K1.w};
        float k2a[4] = {K2.x, K2.y, K2.z, K2.w};

#pragma unroll
        for (int it = 0; it < 4; it++) {
            int r = mrow + 4 * it + (lane >> 3);   // row-in-tile, warp-local
            int row = base + r;
            float4 p4 = make_float4(0.f, 0.f, 0.f, 0.f);
            float4 r4 = make_float4(0.f, 0.f, 0.f, 0.f);
            float4 d4 = make_float4(0.f, 0.f, 0.f, 0.f);
            if (row < nrows) {
                const float4* rp = (const float4*)(in + (size_t)row * 96);
                p4 = rp[q];
                r4 = rp[8 + q];
                d4 = rp[16 + q];
            }
            float px[4] = {p4.x, p4.y, p4.z, p4.w};
            float rx[4] = {r4.x, r4.y, r4.z, r4.w};
            float dx[4] = {d4.x, d4.y, d4.z, d4.w};
            float X[4], Y[4], F[4];
#pragma unroll
            for (int e = 0; e < 4; e++) {
                float s, c;
                __sincosf(px[e], &s, &c);
                X[e] = rx[e] * s;
                Y[e] = rx[e] * c;
                F[e] = fmaf(-k2a[e], dx[e], fmaf(-k1a[e], rx[e], k0a[e]));
            }
            // psi cache for the register-fused epilogue (warp-local rows).
            *(float4*)(smem + OFF_PSI + (u32)(r * PSI_STRIDE + q * 16)) = p4;

            __nv_bfloat162 xh01 = __floats2bfloat162_rn(X[0], X[1]);
            __nv_bfloat162 xh23 = __floats2bfloat162_rn(X[2], X[3]);
            __nv_bfloat162 yh01 = __floats2bfloat162_rn(Y[0], Y[1]);
            __nv_bfloat162 yh23 = __floats2bfloat162_rn(Y[2], Y[3]);
            __nv_bfloat162 xl01 = __floats2bfloat162_rn(X[0] - __bfloat162float(xh01.x),
                                                        X[1] - __bfloat162float(xh01.y));
            __nv_bfloat162 xl23 = __floats2bfloat162_rn(X[2] - __bfloat162float(xh23.x),
                                                        X[3] - __bfloat162float(xh23.y));
            __nv_bfloat162 yl01 = __floats2bfloat162_rn(Y[0] - __bfloat162float(yh01.x),
                                                        Y[1] - __bfloat162float(yh01.y));
            __nv_bfloat162 yl23 = __floats2bfloat162_rn(Y[2] - __bfloat162float(yh23.x),
                                                        Y[3] - __bfloat162float(yh23.y));
            u32 xo = r * A_STRIDE + q * 8;
            u32 yo = xo + 64;
            *(uint2*)(smem + OFF_AHI + xo) = make_uint2(*(u32*)&xh01, *(u32*)&xh23);
            *(uint2*)(smem + OFF_AHI + yo) = make_uint2(*(u32*)&yh01, *(u32*)&yh23);
            *(uint2*)(smem + OFF_ALO + xo) = make_uint2(*(u32*)&xl01, *(u32*)&xl23);
            *(uint2*)(smem + OFF_ALO + yo) = make_uint2(*(u32*)&yl01, *(u32*)&yl23);

            if (row < nrows) {
                float4* op = (float4*)(out + (size_t)row * 96);
                op[8 + q] = d4;                                   // r_d
                op[16 + q] = make_float4(F[0], F[1], F[2], F[3]); // r_d_dot
            }
        }
    }
    __syncwarp();   // warp-private A/psi rows visible to this warp's ldmatrix

    // ---- MMA: warp owns 16 rows x 64 cols; Bhi fragments loaded once per ks ----
    float acc[8][4];
#pragma unroll
    for (int nt = 0; nt < 8; nt++)
#pragma unroll
        for (int e = 0; e < 4; e++) acc[nt][e] = 0.0f;

    int lrow = lane & 15;
    int lhalf = lane >> 4;

#pragma unroll
    for (int ks = 0; ks < 4; ks++) {
        u32 kb = ks * 32 + lhalf * 16;
        u32 ahi[4], alo[4];
        ldm4(ahi, sb + OFF_AHI + (u32)((mrow + lrow) * A_STRIDE) + kb);
        ldm4(alo, sb + OFF_ALO + (u32)((mrow + lrow) * A_STRIDE) + kb);
        u32 bh[4][4];
#pragma unroll
        for (int nb = 0; nb < 4; nb++)
            ldm4(bh[nb], sb + OFF_BHI + (u32)((nb * 16 + lrow) * B_STRIDE) + kb);
#pragma unroll
        for (int nb = 0; nb < 4; nb++) {
            mma16816(acc[2 * nb + 0], ahi, bh[nb][0], bh[nb][2]);
            mma16816(acc[2 * nb + 1], ahi, bh[nb][1], bh[nb][3]);
            mma16816(acc[2 * nb + 0], alo, bh[nb][0], bh[nb][2]);
            mma16816(acc[2 * nb + 1], alo, bh[nb][1], bh[nb][3]);
        }
        u32 bl[4][4];
#pragma unroll
        for (int nb = 0; nb < 4; nb++)
            ldm4(bl[nb], sb + OFF_BLO + (u32)((nb * 16 + lrow) * B_STRIDE) + kb);
#pragma unroll
        for (int nb = 0; nb < 4; nb++) {
            mma16816(acc[2 * nb + 0], ahi, bl[nb][0], bl[nb][2]);
            mma16816(acc[2 * nb + 1], ahi, bl[nb][1], bl[nb][3]);
        }
    }

    // ---- register-fused epilogue: fragment (row,col) -> psi_dot -> STG.64 ----
    // acc[nt][0..1] = row mrow+g, cols nt*8+tc+{0,1}; acc[nt][2..3] = row +8.
    // nt<4 => P, nt>=4 => Q(col-32).
    {
        int g = lane >> 2;
        int tc = (lane & 3) * 2;
        int r0 = mrow + g;
        int row0 = base + r0;
        int row1 = row0 + 8;
#pragma unroll
        for (int cp = 0; cp < 4; cp++) {
            int col = cp * 8 + tc;
            float2 tp = *(const float2*)(smem + OFF_TPV + col * 4);
            float2 ps0 = *(const float2*)(smem + OFF_PSI + (u32)(r0 * PSI_STRIDE + col * 4));
            float2 ps1 = *(const float2*)(smem + OFF_PSI + (u32)((r0 + 8) * PSI_STRIDE + col * 4));
            float s, c;
            __sincosf(ps0.x, &s, &c);
            float v0 = fmaf(c, acc[cp][0], fmaf(-s, acc[cp + 4][0], tp.x));
            __sincosf(ps0.y, &s, &c);
            float v1 = fmaf(c, acc[cp][1], fmaf(-s, acc[cp + 4][1], tp.y));
            __sincosf(ps1.x, &s, &c);
            float w0 = fmaf(c, acc[cp][2], fmaf(-s, acc[cp + 4][2], tp.x));
            __sincosf(ps1.y, &s, &c);
            float w1 = fmaf(c, acc[cp][3], fmaf(-s, acc[cp + 4][3], tp.y));
            if (row0 < nrows)
                *(float2*)(out + (size_t)row0 * 96 + col) = make_float2(v0, v1);
            if (row1 < nrows)
                *(float2*)(out + (size_t)row1 * 96 + col) = make_float2(w0, w1);
        }
    }
}

extern "C" void kernel_launch(void* const* d_in, const int* in_sizes, int n_in,
                              void* d_out, int out_size)
{
    const float* states = (const float*)d_in[0];
    const float* v = (const float*)d_in[1];
    const float* b = (const float*)d_in[2];
    const float* c = (const float*)d_in[3];
    const float* w = (const float*)d_in[4];
    const float* phi = (const float*)d_in[5];
    int nrows = in_sizes[0] / 96;

    cudaFuncSetAttribute(hopf_kernel, cudaFuncAttributeMaxDynamicSharedMemorySize,
                         SMEM_TOTAL);

    hopf_setup_kernel<<<32, 128>>>(v, b, c, w, phi);

    int grid = (nrows + TILE_ROWS - 1) / TILE_ROWS;
    hopf_kernel<<<grid, 256, SMEM_TOTAL>>>(states, (float*)d_out, nrows);
}

// round 14
// speedup vs baseline: 1.8582x; 1.0737x over previous
#include <cuda_runtime.h>
#include <cuda_bf16.h>
#include <cstdint>

// HopfOscillatorModule, round 14: fragment-direct HMMA.
//   [P|Q](row) = [x|y](row) . M (64x64 const, bf16 3-term split).
// k and n dimensions are PERMUTED (map16: {2t,2t+1,8+2t,8+2t+1} -> {4t..4t+3})
// so that each thread's mma A-fragment elements and D-fragment columns fall on
// 8 contiguous oscillators it loads itself via LDG.128. A tiles, psi cache and
// A-side ldmatrix are gone; only B lives in SMEM (18.4KB). sincos computed
// once, reused by the epilogue from registers.

#define NOSC 32
#define TILE_ROWS 128
#define TWO_PI 6.283185307179586f

typedef unsigned int u32;

#define B_STRIDE 144

__device__ __align__(16) unsigned char g_Bhi[64 * B_STRIDE];
__device__ __align__(16) unsigned char g_Blo[64 * B_STRIDE];
__device__ __align__(16) float g_K0[NOSC];
__device__ __align__(16) float g_K1[NOSC];
__device__ __align__(16) float g_K2[NOSC];
__device__ __align__(16) float g_tpv[NOSC];

__device__ __forceinline__ float sigmoidf_(float x) { return 1.0f / (1.0f + expf(-x)); }

// fragment-order map within a 16-block: w = 2t+d (u=0) or 8+2t+d (u=1) -> 4t+2u+d
__device__ __forceinline__ int map16(int w) {
    int u = (w >> 3) & 1, t = (w >> 1) & 3, d = w & 1;
    return 4 * t + 2 * u + d;
}

// ---------------- setup: 32 CTAs, one B-entry per thread ----------------
__global__ void hopf_setup_kernel(const float* __restrict__ v, const float* __restrict__ b,
                                  const float* __restrict__ c, const float* __restrict__ w,
                                  const float* __restrict__ phi)
{
    int tid = threadIdx.x;
    if (blockIdx.x == 0 && tid < NOSC) {
        float va = 5.0f * sigmoidf_(v[tid]);
        float ba = 2.0f * sigmoidf_(b[tid]);
        float ca = 10.0f * sigmoidf_(c[tid]);
        float K1 = 0.25f * ca * ca;
        g_K0[tid] = K1 * ba;
        g_K1[tid] = K1;
        g_K2[tid] = ca;
        g_tpv[tid] = TWO_PI * va;
    }
    int e = blockIdx.x * 128 + tid;            // 0..4095
    int n = e >> 6, k = e & 63;
    // k -> (is_x, j) with fragment permutation
    int ks = k >> 4;
    int j = ((ks & 1) << 4) + map16(k & 15);
    bool is_x = (ks < 2);
    // n -> (P/Q, oscillator i) with the same permutation
    int p = n >> 5;
    int m = n & 31;
    int i = ((m >> 4) << 4) + map16(m & 15);
    int flat = 32 * i + j;                     // index into zero-diag 32x32
    float A = 0.0f, Bc = 0.0f;
    if (flat != 1023) {
        // _zero_diag: z = concat([zeros(31,1), P],1).ravel() ++ [0] -> (32,32)
        int t = flat / 33, pos = flat % 33;
        if (pos != 0) {
            float wa = sigmoidf_(w[t * 32 + pos - 1]);            // W_MAX = 1
            float pa = TWO_PI * sigmoidf_(phi[t * 32 + pos - 1]);
            float sp, cp;
            sincosf(pa, &sp, &cp);
            A = wa * cp;
            Bc = wa * sp;
        }
    }
    float Mf;
    if (p == 0) Mf = is_x ? A : -Bc;     // P part
    else        Mf = is_x ? Bc : A;      // Q part
    __nv_bfloat16 hi = __float2bfloat16_rn(Mf);
    __nv_bfloat16 lo = __float2bfloat16_rn(Mf - __bfloat162float(hi));
    *(__nv_bfloat16*)(g_Bhi + n * B_STRIDE + k * 2) = hi;
    *(__nv_bfloat16*)(g_Blo + n * B_STRIDE + k * 2) = lo;
}

// ---------------- ptx helpers ----------------
__device__ __forceinline__ u32 smem_u32(const void* p) {
    u32 a;
    asm("{ .reg .u64 t; cvta.to.shared.u64 t, %1; cvt.u32.u64 %0, t; }" : "=r"(a) : "l"(p));
    return a;
}
__device__ __forceinline__ void ldm4(u32* r, u32 addr) {
    asm volatile("ldmatrix.sync.aligned.m8n8.x4.shared.b16 {%0,%1,%2,%3}, [%4];"
                 : "=r"(r[0]), "=r"(r[1]), "=r"(r[2]), "=r"(r[3]) : "r"(addr));
}
__device__ __forceinline__ void mma16816(float* d, u32 a0, u32 a1, u32 a2, u32 a3,
                                         u32 b0, u32 b1) {
    asm volatile(
        "mma.sync.aligned.m16n8k16.row.col.f32.bf16.bf16.f32 "
        "{%0,%1,%2,%3}, {%4,%5,%6,%7}, {%8,%9}, {%0,%1,%2,%3};"
        : "+f"(d[0]), "+f"(d[1]), "+f"(d[2]), "+f"(d[3])
        : "r"(a0), "r"(a1), "r"(a2), "r"(a3), "r"(b0), "r"(b1));
}

// ---------------- main kernel ----------------
__global__ __launch_bounds__(256, 2)
void hopf_kernel(const float* __restrict__ in, float* __restrict__ out, int nrows)
{
    __shared__ __align__(16) unsigned char sBhi[64 * B_STRIDE];
    __shared__ __align__(16) unsigned char sBlo[64 * B_STRIDE];

    int tid = threadIdx.x;
    int lane = tid & 31;
    int wid = tid >> 5;
    u32 sbh = smem_u32(sBhi);
    u32 sbl = smem_u32(sBlo);

    // Stage constant B tiles (LDG->STS); barrier comes AFTER the prologue.
    {
        const uint4* gh = (const uint4*)g_Bhi;
        const uint4* gl = (const uint4*)g_Blo;
        uint4* sh = (uint4*)sBhi;
        uint4* sl = (uint4*)sBlo;
        for (int i = tid; i < (64 * B_STRIDE) / 16; i += 256) {
            sh[i] = gh[i];
            sl[i] = gl[i];
        }
    }

    int g = lane >> 2;
    int t = lane & 3;
    int base = blockIdx.x * TILE_ROWS;
    int mrow = wid * 16;

    // sincos + fragment registers. [r] = row g / g+8; [h] = j-chunk 16h+4t.
    float S[2][2][4], C[2][2][4];
    u32 XH[2][4], XL[2][4], YH[2][4], YL[2][4];   // [r][pair]: pairs 2h, 2h+1

    // ---- prologue: LDG.128 -> sincos -> fragments + r_d / r_d_dot stores ----
#pragma unroll
    for (int r = 0; r < 2; r++) {
        int row = base + mrow + g + 8 * r;
        bool ok = row < nrows;
        const float* ip = in + (size_t)row * 96;
        float* op = out + (size_t)row * 96;
#pragma unroll
        for (int h = 0; h < 2; h++) {
            int j0 = 16 * h + 4 * t;
            float4 p4 = ok ? *(const float4*)(ip + j0) : make_float4(0.f, 0.f, 0.f, 0.f);
            float4 r4 = ok ? *(const float4*)(ip + 32 + j0) : make_float4(0.f, 0.f, 0.f, 0.f);
            float4 d4 = ok ? *(const float4*)(ip + 64 + j0) : make_float4(0.f, 0.f, 0.f, 0.f);
            float4 K0 = ((const float4*)g_K0)[4 * h + t];
            float4 K1 = ((const float4*)g_K1)[4 * h + t];
            float4 K2 = ((const float4*)g_K2)[4 * h + t];
            float px[4] = {p4.x, p4.y, p4.z, p4.w};
            float rx[4] = {r4.x, r4.y, r4.z, r4.w};
            float dx[4] = {d4.x, d4.y, d4.z, d4.w};
            float k0a[4] = {K0.x, K0.y, K0.z, K0.w};
            float k1a[4] = {K1.x, K1.y, K1.z, K1.w};
            float k2a[4] = {K2.x, K2.y, K2.z, K2.w};
            float X[4], Y[4], F[4];
#pragma unroll
            for (int e = 0; e < 4; e++) {
                float s, c;
                __sincosf(px[e], &s, &c);
                S[r][h][e] = s;
                C[r][h][e] = c;
                X[e] = rx[e] * s;
                Y[e] = rx[e] * c;
                F[e] = fmaf(-k2a[e], dx[e], fmaf(-k1a[e], rx[e], k0a[e]));
            }
            __nv_bfloat162 xh0 = __floats2bfloat162_rn(X[0], X[1]);
            __nv_bfloat162 xh1 = __floats2bfloat162_rn(X[2], X[3]);
            __nv_bfloat162 yh0 = __floats2bfloat162_rn(Y[0], Y[1]);
            __nv_bfloat162 yh1 = __floats2bfloat162_rn(Y[2], Y[3]);
            __nv_bfloat162 xl0 = __floats2bfloat162_rn(X[0] - __bfloat162float(xh0.x),
                                                       X[1] - __bfloat162float(xh0.y));
            __nv_bfloat162 xl1 = __floats2bfloat162_rn(X[2] - __bfloat162float(xh1.x),
                                                       X[3] - __bfloat162float(xh1.y));
            __nv_bfloat162 yl0 = __floats2bfloat162_rn(Y[0] - __bfloat162float(yh0.x),
                                                       Y[1] - __bfloat162float(yh0.y));
            __nv_bfloat162 yl1 = __floats2bfloat162_rn(Y[2] - __bfloat162float(yh1.x),
                                                       Y[3] - __bfloat162float(yh1.y));
            XH[r][2 * h] = *(u32*)&xh0;
            XH[r][2 * h + 1] = *(u32*)&xh1;
            XL[r][2 * h] = *(u32*)&xl0;
            XL[r][2 * h + 1] = *(u32*)&xl1;
            YH[r][2 * h] = *(u32*)&yh0;
            YH[r][2 * h + 1] = *(u32*)&yh1;
            YL[r][2 * h] = *(u32*)&yl0;
            YL[r][2 * h + 1] = *(u32*)&yl1;
            if (ok) {
                *(float4*)(op + 32 + j0) = d4;                                // r_d
                *(float4*)(op + 64 + j0) = make_float4(F[0], F[1], F[2], F[3]); // r_d_dot
            }
        }
    }
    __syncthreads();   // B tiles ready (staging overlapped with prologue)

    // ---- MMA: A fragments straight from registers, B via ldmatrix ----
    float acc[8][4];
#pragma unroll
    for (int nt = 0; nt < 8; nt++)
#pragma unroll
        for (int e = 0; e < 4; e++) acc[nt][e] = 0.0f;

    int lrow = lane & 15;
    int lhalf = lane >> 4;

#pragma unroll
    for (int ks = 0; ks < 4; ks++) {
        u32 kb = ks * 32 + lhalf * 16;
        int p = (ks & 1) * 2;              // fragment pair base for this chunk
        u32 ah0, ah1, ah2, ah3, al0, al1, al2, al3;
        if (ks < 2) {
            ah0 = XH[0][p]; ah1 = XH[1][p]; ah2 = XH[0][p + 1]; ah3 = XH[1][p + 1];
            al0 = XL[0][p]; al1 = XL[1][p]; al2 = XL[0][p + 1]; al3 = XL[1][p + 1];
        } else {
            ah0 = YH[0][p]; ah1 = YH[1][p]; ah2 = YH[0][p + 1]; ah3 = YH[1][p + 1];
            al0 = YL[0][p]; al1 = YL[1][p]; al2 = YL[0][p + 1]; al3 = YL[1][p + 1];
        }
        u32 bh[4][4];
#pragma unroll
        for (int nb = 0; nb < 4; nb++)
            ldm4(bh[nb], sbh + (u32)((nb * 16 + lrow) * B_STRIDE) + kb);
#pragma unroll
        for (int nb = 0; nb < 4; nb++) {
            mma16816(acc[2 * nb + 0], ah0, ah1, ah2, ah3, bh[nb][0], bh[nb][2]);
            mma16816(acc[2 * nb + 1], ah0, ah1, ah2, ah3, bh[nb][1], bh[nb][3]);
            mma16816(acc[2 * nb + 0], al0, al1, al2, al3, bh[nb][0], bh[nb][2]);
            mma16816(acc[2 * nb + 1], al0, al1, al2, al3, bh[nb][1], bh[nb][3]);
        }
        u32 bl[4][4];
#pragma unroll
        for (int nb = 0; nb < 4; nb++)
            ldm4(bl[nb], sbl + (u32)((nb * 16 + lrow) * B_STRIDE) + kb);
#pragma unroll
        for (int nb = 0; nb < 4; nb++) {
            mma16816(acc[2 * nb + 0], ah0, ah1, ah2, ah3, bl[nb][0], bl[nb][2]);
            mma16816(acc[2 * nb + 1], ah0, ah1, ah2, ah3, bl[nb][1], bl[nb][3]);
        }
    }

    // ---- epilogue: psi_dot from fragments + register sincos -> STG.128 ----
    // D col n -> oscillator i via map16; thread's cols land on i = 16h+4t+e,
    // P = acc[2h + (e>>1)], Q = acc[4 + 2h + (e>>1)], element (e&1) + 2r.
#pragma unroll
    for (int r = 0; r < 2; r++) {
        int row = base + mrow + g + 8 * r;
        if (row < nrows) {
            float* op = out + (size_t)row * 96;
#pragma unroll
            for (int h = 0; h < 2; h++) {
                float4 tp = ((const float4*)g_tpv)[4 * h + t];
                float tpa[4] = {tp.x, tp.y, tp.z, tp.w};
                float v[4];
#pragma unroll
                for (int e = 0; e < 4; e++) {
                    int cp = 2 * h + (e >> 1);
                    int el = (e & 1) + 2 * r;
                    v[e] = fmaf(C[r][h][e], acc[cp][el],
                                fmaf(-S[r][h][e], acc[cp + 4][el], tpa[e]));
                }
                *(float4*)(op + 16 * h + 4 * t) = make_float4(v[0], v[1], v[2], v[3]);
            }
        }
    }
}

extern "C" void kernel_launch(void* const* d_in, const int* in_sizes, int n_in,
                              void* d_out, int out_size)
{
    const float* states = (const float*)d_in[0];
    const float* v = (const float*)d_in[1];
    const float* b = (const float*)d_in[2];
    const float* c = (const float*)d_in[3];
    const float* w = (const float*)d_in[4];
    const float* phi = (const float*)d_in[5];
    int nrows = in_sizes[0] / 96;

    hopf_setup_kernel<<<32, 128>>>(v, b, c, w, phi);

    int grid = (nrows + TILE_ROWS - 1) / TILE_ROWS;
    hopf_kernel<<<grid, 256>>>(states, (float*)d_out, nrows);
}